// round 14
// baseline (speedup 1.0000x reference)
#include <cuda_runtime.h>

// Problem constants
#define BB 2
#define BN 4096
#define PARTS 32
#define CPART (BN / PARTS)       // 128 columns per partition
#define TPB 128                  // threads per block (4 warps)
#define RPB 256                  // rows per block (2 adjacent rows per thread)
#define ROWTILES (BN / RPB)      // 16
#define LOG2E 1.4426950408889634f
#define LN2 0.6931471805599453f
#define CULL 30.0f               // log2-units skip margin

// Scratch (allocation-free). Sorted point sets as float4 (x,y,z, 0.5*||p||^2).
__device__ float4 gXs4[BB * BN];
__device__ float4 gYs4[BB * BN];
__device__ float g_ax[BB * BN];
__device__ float g_by[BB * BN];
__device__ float g_bx[BB * BN];
__device__ float g_ay[BB * BN];
__device__ float g_pm[4 * BB * PARTS * BN];
__device__ float g_ps[4 * BB * PARTS * BN];
__device__ float g_bb[2 * BB * PARTS * 8];   // per-partition bbox: lo0,lo1,lo2,hi0,hi1,hi2

__device__ __forceinline__ float ex2f(float x) {
    float r;
    asm("ex2.approx.f32 %0, %1;" : "=f"(r) : "f"(x));
    return r;
}
__device__ __forceinline__ float lg2f(float x) {
    float r;
    asm("lg2.approx.f32 %0, %1;" : "=f"(r) : "f"(x));
    return r;
}
__device__ __forceinline__ unsigned int ebits(unsigned int x) {
    x &= 0x3FFu;
    x = (x | (x << 16)) & 0x030000FFu;
    x = (x | (x << 8))  & 0x0300F00Fu;
    x = (x | (x << 4))  & 0x030C30C3u;
    x = (x | (x << 2))  & 0x09249249u;
    return x;
}

// Morton-sort one (set,batch) of 4096 points via in-smem bitonic; write sorted float4.
__global__ __launch_bounds__(1024) void sort_kernel(const float* __restrict__ X,
                                                    const float* __restrict__ Y) {
    __shared__ unsigned long long sk[BN];
    int blk = blockIdx.x;
    int set = blk >> 1, b = blk & 1;
    const float* P = set ? Y : X;
    float4* out = set ? gYs4 : gXs4;
    int tid = threadIdx.x;

    for (int i = tid; i < BN; i += 1024) {
        int gi = (b * BN + i) * 3;
        float c0 = P[gi], c1 = P[gi + 1], c2 = P[gi + 2];
        unsigned int qx = (unsigned int)fminf(fmaxf((c0 + 8.0f) * 64.0f, 0.0f), 1023.0f);
        unsigned int qy = (unsigned int)fminf(fmaxf((c1 + 8.0f) * 64.0f, 0.0f), 1023.0f);
        unsigned int qz = (unsigned int)fminf(fmaxf((c2 + 8.0f) * 64.0f, 0.0f), 1023.0f);
        unsigned int m = (ebits(qx) << 2) | (ebits(qy) << 1) | ebits(qz);
        sk[i] = ((unsigned long long)m << 12) | (unsigned int)i;
    }
    __syncthreads();

    for (int k = 2; k <= BN; k <<= 1) {
        for (int j = k >> 1; j > 0; j >>= 1) {
            for (int t = tid; t < BN / 2; t += 1024) {
                int i = 2 * t - (t & (j - 1));
                int p = i + j;
                bool up = ((i & k) == 0);
                unsigned long long a = sk[i], c = sk[p];
                if ((a > c) == up) { sk[i] = c; sk[p] = a; }
            }
            __syncthreads();
        }
    }

    for (int i = tid; i < BN; i += 1024) {
        int src = (int)(sk[i] & 0xFFFu);
        int gs = (b * BN + src) * 3;
        float c0 = P[gs], c1 = P[gs + 1], c2 = P[gs + 2];
        out[b * BN + i] = make_float4(c0, c1, c2, 0.5f * (c0 * c0 + c1 * c1 + c2 * c2));
    }
}

// Per-partition bounding boxes (stage-invariant, after sort).
__global__ __launch_bounds__(CPART) void bbox_kernel() {
    __shared__ float sred[4];
    int blk = blockIdx.x;
    int part = blk & (PARTS - 1), b = (blk >> 5) & 1, set = blk >> 6;
    const float4* S = set ? gYs4 : gXs4;
    float4 c = S[b * BN + part * CPART + threadIdx.x];
    float* out = &g_bb[((set * BB + b) * PARTS + part) * 8];
    int tid = threadIdx.x, lane = tid & 31, w = tid >> 5;

    float vals[6] = {c.x, c.y, c.z, c.x, c.y, c.z};
#pragma unroll
    for (int q = 0; q < 6; q++) {
        float v = vals[q];
        if (q < 3) {
#pragma unroll
            for (int o = 16; o; o >>= 1) v = fminf(v, __shfl_xor_sync(0xFFFFFFFFu, v, o));
        } else {
#pragma unroll
            for (int o = 16; o; o >>= 1) v = fmaxf(v, __shfl_xor_sync(0xFFFFFFFFu, v, o));
        }
        if (lane == 0) sred[w] = v;
        __syncthreads();
        if (tid == 0) {
            float r = (q < 3) ? fminf(fminf(sred[0], sred[1]), fminf(sred[2], sred[3]))
                              : fmaxf(fmaxf(sred[0], sred[1]), fmaxf(sred[2], sred[3]));
            out[q] = r;
        }
        __syncthreads();
    }
}

// One stage: 4 softmins. Scalar log2-domain online LSE + sorted-data partition culling.
// v_ij = g_j + (x_i*log2e/eps).y_j,  g_j = -12 + (dual_j*ds - q_j)*log2e/eps
// Skip whole partition per thread when ub (bbox+maxg bound) < lb (real v at j*=row rank) - CULL.
// Tasks: t0: C_xx h=a_x | t1: C_yy h=b_y | t2: C_xy h=a_y -> b_x | t3: C_yx h=b_x -> a_y
__global__ __launch_bounds__(TPB) void softmin_kernel(float eps, float dualScale) {
    __shared__ float4 shY[CPART];   // (y0, y1, y2, g)
    __shared__ float swarp[4];

    int bi = blockIdx.x;
    int part    = bi & (PARTS - 1);
    int rowTile = (bi >> 5) & (ROWTILES - 1);
    int b       = (bi >> 9) & (BB - 1);
    int task    = bi >> 10;

    const float4* rowS = (task == 0 || task == 2) ? gXs4 : gYs4;
    const float4* colS = (task == 0 || task == 3) ? gXs4 : gYs4;
    int cset           = (task == 0 || task == 3) ? 0 : 1;
    const float* colD = (task == 0) ? g_ax : (task == 1) ? g_by : (task == 2) ? g_ay : g_bx;

    const float sLe = LOG2E / eps;
    int tid = threadIdx.x;

    // Load one column per thread; fold dual+norm into g.
    int gj = b * BN + part * CPART + tid;
    float4 yv = colS[gj];
    float gcol = -12.0f + (colD[gj] * dualScale - yv.w) * sLe;
    shY[tid] = make_float4(yv.x, yv.y, yv.z, gcol);

    // Block-level max of g over this partition
    float gv = gcol;
#pragma unroll
    for (int o = 16; o; o >>= 1) gv = fmaxf(gv, __shfl_xor_sync(0xFFFFFFFFu, gv, o));
    if ((tid & 31) == 0) swarp[tid >> 5] = gv;
    __syncthreads();
    float maxg = fmaxf(fmaxf(swarp[0], swarp[1]), fmaxf(swarp[2], swarp[3]));

    // Two ADJACENT sorted rows per thread (warp-coherent culling)
    int r0 = rowTile * RPB + 2 * tid;
    int r1 = r0 + 1;
    int g0 = b * BN + r0, g1 = b * BN + r1;
    float4 xv0 = rowS[g0], xv1 = rowS[g1];
    float xa0 = xv0.x * sLe, xa1 = xv0.y * sLe, xa2 = xv0.z * sLe;
    float xb0 = xv1.x * sLe, xb1 = xv1.y * sLe, xb2 = xv1.z * sLe;

    // Upper bound over this partition (bbox in raw coords; xs pre-scaled by sLe>0)
    const float* bb = &g_bb[((cset * BB + b) * PARTS + part) * 8];
    float lo0 = bb[0], lo1 = bb[1], lo2 = bb[2], hi0 = bb[3], hi1 = bb[4], hi2 = bb[5];
    float ub0 = maxg + fmaxf(xa0 * lo0, xa0 * hi0) + fmaxf(xa1 * lo1, xa1 * hi1)
                     + fmaxf(xa2 * lo2, xa2 * hi2);
    float ub1 = maxg + fmaxf(xb0 * lo0, xb0 * hi0) + fmaxf(xb1 * lo1, xb1 * hi1)
                     + fmaxf(xb2 * lo2, xb2 * hi2);

    // Lower bound: true v at candidate column j* = same sorted rank
    float4 cj0 = colS[g0];
    float4 cj1 = colS[g1];
    float gq0 = -12.0f + (colD[g0] * dualScale - cj0.w) * sLe;
    float gq1 = -12.0f + (colD[g1] * dualScale - cj1.w) * sLe;
    float lb0 = fmaf(xa0, cj0.x, fmaf(xa1, cj0.y, fmaf(xa2, cj0.z, gq0)));
    float lb1 = fmaf(xb0, cj1.x, fmaf(xb1, cj1.y, fmaf(xb2, cj1.z, gq1)));

    int base = ((task * BB + b) * PARTS + part) * BN;
    if (ub0 + CULL < lb0 && ub1 + CULL < lb1) {
        // whole partition negligible for both rows: contribution < 2^-23 relative
        *(float2*)&g_pm[base + r0] = make_float2(-3.0e38f, -3.0e38f);
        *(float2*)&g_ps[base + r0] = make_float2(0.f, 0.f);
        return;
    }

    float m0 = -3.0e38f, m1 = -3.0e38f;
    float s0a = 0.f, s0b = 0.f, s1a = 0.f, s1b = 0.f;

    for (int p = 0; p < CPART; p += 8) {
        float va[8], vb[8];
#pragma unroll
        for (int k = 0; k < 8; k++) {
            float4 c = shY[p + k];
            va[k] = fmaf(xa0, c.x, fmaf(xa1, c.y, fmaf(xa2, c.z, c.w)));
            vb[k] = fmaf(xb0, c.x, fmaf(xb1, c.y, fmaf(xb2, c.z, c.w)));
        }
        float ca = fmaxf(fmaxf(fmaxf(va[0], va[1]), fmaxf(va[2], va[3])),
                         fmaxf(fmaxf(va[4], va[5]), fmaxf(va[6], va[7])));
        float cb = fmaxf(fmaxf(fmaxf(vb[0], vb[1]), fmaxf(vb[2], vb[3])),
                         fmaxf(fmaxf(vb[4], vb[5]), fmaxf(vb[6], vb[7])));
        float mna = fmaxf(m0, ca);
        float mnb = fmaxf(m1, cb);
        float sca = ex2f(m0 - mna);
        float scb = ex2f(m1 - mnb);
        s0a *= sca; s0b *= sca; m0 = mna;
        s1a *= scb; s1b *= scb; m1 = mnb;
#pragma unroll
        for (int k = 0; k < 8; k += 2) {
            s0a += ex2f(va[k] - m0);
            s0b += ex2f(va[k + 1] - m0);
            s1a += ex2f(vb[k] - m1);
            s1b += ex2f(vb[k + 1] - m1);
        }
    }

    *(float2*)&g_pm[base + r0] = make_float2(m0, m1);
    *(float2*)&g_ps[base + r0] = make_float2(s0a + s0b, s1a + s1b);
}

// Combine partition partials -> softmin value; optionally average with old dual (in place).
__global__ void merge_kernel(float eps, int avg) {
    int idx = blockIdx.x * blockDim.x + threadIdx.x;
    if (idx >= 4 * BB * BN) return;
    int task = idx / (BB * BN);
    int rem  = idx - task * (BB * BN);

    float rq = (task == 0 || task == 2) ? gXs4[rem].w : gYs4[rem].w;
    float* outA = (task == 0) ? g_ax : (task == 1) ? g_by : (task == 2) ? g_bx : g_ay;

    int b = rem / BN;
    int r = rem - b * BN;
    int base = (task * BB + b) * (PARTS * BN) + r;
    float M = -3.0e38f;
#pragma unroll
    for (int p = 0; p < PARTS; p++) M = fmaxf(M, g_pm[base + p * BN]);
    float s = 0.f;
#pragma unroll
    for (int p = 0; p < PARTS; p++)
        s = fmaf(g_ps[base + p * BN], ex2f(g_pm[base + p * BN] - M), s);

    float sLe = LOG2E / eps;
    float ri  = -rq * sLe;
    float val = -eps * LN2 * (ri + M + lg2f(s));
    if (avg) val = 0.5f * (outA[rem] + val);
    outA[rem] = val;
}

// F = sum_b [ (1/N) sum_i (b_x - a_x) + (1/M) sum_j (a_y - b_y) ]  (order-invariant)
__global__ void reduce_kernel(float* __restrict__ out) {
    __shared__ float sh[32];
    int tid = threadIdx.x;
    float acc = 0.f;
    for (int i = tid; i < BB * BN; i += blockDim.x)
        acc += (g_bx[i] - g_ax[i]) + (g_ay[i] - g_by[i]);
    acc *= (1.0f / BN);
#pragma unroll
    for (int o = 16; o; o >>= 1) acc += __shfl_down_sync(0xFFFFFFFFu, acc, o);
    if ((tid & 31) == 0) sh[tid >> 5] = acc;
    __syncthreads();
    if (tid < 32) {
        float v = (tid < (int)(blockDim.x >> 5)) ? sh[tid] : 0.f;
#pragma unroll
        for (int o = 16; o; o >>= 1) v += __shfl_down_sync(0xFFFFFFFFu, v, o);
        if (tid == 0) out[0] = v;
    }
}

extern "C" void kernel_launch(void* const* d_in, const int* in_sizes, int n_in,
                              void* d_out, int out_size) {
    const float* X = (const float*)d_in[0];   // true_data
    const float* Y = (const float*)d_in[1];   // particles
    float* out = (float*)d_out;

    sort_kernel<<<4, 1024>>>(X, Y);           // Morton sort + norms
    bbox_kernel<<<2 * BB * PARTS, CPART>>>(); // per-partition bboxes

    // geomloss eps schedule: [16] + [16,4,1,0.25,0.0625,0.015625,0.00390625] + [0.0025]
    const float epsList[9] = {16.f, 16.f, 4.f, 1.f, 0.25f, 0.0625f,
                              0.015625f, 0.00390625f, 0.0025f};

    const int gridSoft = 4 * BB * ROWTILES * PARTS;   // 4096 blocks
    const int gridMerge = (4 * BB * BN) / 256;        // 128 blocks

    // init (dual term off, assignment)
    softmin_kernel<<<gridSoft, TPB>>>(16.f, 0.f);
    merge_kernel<<<gridMerge, 256>>>(16.f, 0);

    // eps-scaling loop (symmetrized, averaged updates)
    for (int e = 0; e < 9; e++) {
        softmin_kernel<<<gridSoft, TPB>>>(epsList[e], 1.f);
        merge_kernel<<<gridMerge, 256>>>(epsList[e], 1);
    }

    // final extrapolation at blur^2 (assignment, no averaging)
    softmin_kernel<<<gridSoft, TPB>>>(0.0025f, 1.f);
    merge_kernel<<<gridMerge, 256>>>(0.0025f, 0);

    reduce_kernel<<<1, 256>>>(out);
}

// round 17
// speedup vs baseline: 1.0589x; 1.0589x over previous
#include <cuda_runtime.h>

// Problem constants
#define BB 2
#define BN 4096
#define PARTS 32
#define CPART (BN / PARTS)       // 128 columns per partition
#define TPB 128                  // threads per block (4 warps)
#define RPB 256                  // rows per block (2 rows per thread)
#define ROWTILES (BN / RPB)      // 16
#define LOG2E 1.4426950408889634f
#define LN2 0.6931471805599453f
#define CULL 20.0f               // log2-units skip margin

// Scratch (allocation-free). Sorted point sets as float4 (x,y,z, 0.5*||p||^2).
__device__ float4 gXs4[BB * BN];
__device__ float4 gYs4[BB * BN];
// Ping-pong dual buffers: [parity][dual d * BB*BN + idx], d: 0=a_x 1=b_y 2=b_x 3=a_y
__device__ float g_du[2][4 * BB * BN];
__device__ float g_pm[4 * BB * PARTS * BN];
__device__ float g_ps[4 * BB * PARTS * BN];
__device__ float g_bb[2 * BB * PARTS * 8];   // per-partition bbox
__device__ int   g_cnt[4 * BB * ROWTILES];   // zero-init; self-resetting arrival counters

__device__ __forceinline__ float ex2f(float x) {
    float r;
    asm("ex2.approx.f32 %0, %1;" : "=f"(r) : "f"(x));
    return r;
}
__device__ __forceinline__ float lg2f(float x) {
    float r;
    asm("lg2.approx.f32 %0, %1;" : "=f"(r) : "f"(x));
    return r;
}
__device__ __forceinline__ unsigned int ebits(unsigned int x) {
    x &= 0x3FFu;
    x = (x | (x << 16)) & 0x030000FFu;
    x = (x | (x << 8))  & 0x0300F00Fu;
    x = (x | (x << 4))  & 0x030C30C3u;
    x = (x | (x << 2))  & 0x09249249u;
    return x;
}

// Morton-sort one (set,batch) of 4096 points via in-smem bitonic on 32-bit keys.
__global__ __launch_bounds__(1024) void sort_kernel(const float* __restrict__ X,
                                                    const float* __restrict__ Y) {
    __shared__ unsigned int sk[BN];
    int blk = blockIdx.x;
    int set = blk >> 1, b = blk & 1;
    const float* P = set ? Y : X;
    float4* out = set ? gYs4 : gXs4;
    int tid = threadIdx.x;

    for (int i = tid; i < BN; i += 1024) {
        int gi = (b * BN + i) * 3;
        float c0 = P[gi], c1 = P[gi + 1], c2 = P[gi + 2];
        unsigned int qx = (unsigned int)fminf(fmaxf((c0 + 5.0f) * 6.3f, 0.0f), 63.0f);
        unsigned int qy = (unsigned int)fminf(fmaxf((c1 + 5.0f) * 6.3f, 0.0f), 63.0f);
        unsigned int qz = (unsigned int)fminf(fmaxf((c2 + 5.0f) * 6.3f, 0.0f), 63.0f);
        unsigned int m = (ebits(qx) << 2) | (ebits(qy) << 1) | ebits(qz);  // 18 bits
        sk[i] = (m << 12) | (unsigned int)i;
    }
    __syncthreads();

    for (int k = 2; k <= BN; k <<= 1) {
        for (int j = k >> 1; j > 0; j >>= 1) {
            for (int t = tid; t < BN / 2; t += 1024) {
                int i = 2 * t - (t & (j - 1));
                int p = i + j;
                bool up = ((i & k) == 0);
                unsigned int a = sk[i], c = sk[p];
                if ((a > c) == up) { sk[i] = c; sk[p] = a; }
            }
            __syncthreads();
        }
    }

    for (int i = tid; i < BN; i += 1024) {
        int src = (int)(sk[i] & 0xFFFu);
        int gs = (b * BN + src) * 3;
        float c0 = P[gs], c1 = P[gs + 1], c2 = P[gs + 2];
        out[b * BN + i] = make_float4(c0, c1, c2, 0.5f * (c0 * c0 + c1 * c1 + c2 * c2));
    }
}

// Per-partition bounding boxes (stage-invariant, after sort).
__global__ __launch_bounds__(CPART) void bbox_kernel() {
    __shared__ float sred[4];
    int blk = blockIdx.x;
    int part = blk & (PARTS - 1), b = (blk >> 5) & 1, set = blk >> 6;
    const float4* S = set ? gYs4 : gXs4;
    float4 c = S[b * BN + part * CPART + threadIdx.x];
    float* out = &g_bb[((set * BB + b) * PARTS + part) * 8];
    int tid = threadIdx.x, lane = tid & 31, w = tid >> 5;

    float vals[6] = {c.x, c.y, c.z, c.x, c.y, c.z};
#pragma unroll
    for (int q = 0; q < 6; q++) {
        float v = vals[q];
        if (q < 3) {
#pragma unroll
            for (int o = 16; o; o >>= 1) v = fminf(v, __shfl_xor_sync(0xFFFFFFFFu, v, o));
        } else {
#pragma unroll
            for (int o = 16; o; o >>= 1) v = fmaxf(v, __shfl_xor_sync(0xFFFFFFFFu, v, o));
        }
        if (lane == 0) sred[w] = v;
        __syncthreads();
        if (tid == 0) {
            float r = (q < 3) ? fminf(fminf(sred[0], sred[1]), fminf(sred[2], sred[3]))
                              : fmaxf(fmaxf(sred[0], sred[1]), fmaxf(sred[2], sred[3]));
            out[q] = r;
        }
        __syncthreads();
    }
}

// One stage: 4 softmins with partition+chunk culling, FUSED per-row merge by the
// last-arriving block of each (task,b,rowTile) group. Ping-pong duals: read parity rp,
// write parity 1-rp -> no cross-task read/write hazard within a launch.
// Tasks: t0: C_xx rd a_x wr a_x | t1: C_yy rd b_y wr b_y | t2: C_xy rd a_y wr b_x | t3: C_yx rd b_x wr a_y
__global__ __launch_bounds__(TPB) void softmin_kernel(float eps, float dualScale,
                                                      int avg, int rp) {
    __shared__ float4 shY[CPART];   // (y0, y1, y2, g)
    __shared__ float swarp[4];
    __shared__ int sdoer;

    int bi = blockIdx.x;
    int part    = bi & (PARTS - 1);
    int rowTile = (bi >> 5) & (ROWTILES - 1);
    int b       = (bi >> 9) & (BB - 1);
    int task    = bi >> 10;

    const float4* rowS = (task == 0 || task == 2) ? gXs4 : gYs4;
    const float4* colS = (task == 0 || task == 3) ? gXs4 : gYs4;
    int cset           = (task == 0 || task == 3) ? 0 : 1;
    int dread  = (task == 0) ? 0 : (task == 1) ? 1 : (task == 2) ? 3 : 2;
    int dwrite = (task == 0) ? 0 : (task == 1) ? 1 : (task == 2) ? 2 : 3;
    const float* colD    = &g_du[rp][dread * BB * BN];
    const float* outAOld = &g_du[rp][dwrite * BB * BN];
    float*       outA    = &g_du[1 - rp][dwrite * BB * BN];

    const float sLe = LOG2E / eps;
    int tid = threadIdx.x;

    // Load one column per thread; fold dual+norm into g.
    int gj = b * BN + part * CPART + tid;
    float4 yv = colS[gj];
    float gcol = -12.0f + (colD[gj] * dualScale - yv.w) * sLe;
    shY[tid] = make_float4(yv.x, yv.y, yv.z, gcol);

    // Block-level max of g over this partition
    float gv = gcol;
#pragma unroll
    for (int o = 16; o; o >>= 1) gv = fmaxf(gv, __shfl_xor_sync(0xFFFFFFFFu, gv, o));
    if ((tid & 31) == 0) swarp[tid >> 5] = gv;
    __syncthreads();
    float maxg = fmaxf(fmaxf(swarp[0], swarp[1]), fmaxf(swarp[2], swarp[3]));

    // Two ADJACENT sorted rows per thread (warp-coherent culling)
    int r0 = rowTile * RPB + 2 * tid;
    int g0 = b * BN + r0, g1 = g0 + 1;
    float4 xv0 = rowS[g0], xv1 = rowS[g1];
    float xa0 = xv0.x * sLe, xa1 = xv0.y * sLe, xa2 = xv0.z * sLe;
    float xb0 = xv1.x * sLe, xb1 = xv1.y * sLe, xb2 = xv1.z * sLe;

    // Upper bound over this partition (bbox) and lower bound (true v at rank-match j*)
    const float* bb = &g_bb[((cset * BB + b) * PARTS + part) * 8];
    float ub0 = maxg + fmaxf(xa0 * bb[0], xa0 * bb[3]) + fmaxf(xa1 * bb[1], xa1 * bb[4])
                     + fmaxf(xa2 * bb[2], xa2 * bb[5]);
    float ub1 = maxg + fmaxf(xb0 * bb[0], xb0 * bb[3]) + fmaxf(xb1 * bb[1], xb1 * bb[4])
                     + fmaxf(xb2 * bb[2], xb2 * bb[5]);

    float4 cj0 = colS[g0];
    float4 cj1 = colS[g1];
    float gq0 = -12.0f + (colD[g0] * dualScale - cj0.w) * sLe;
    float gq1 = -12.0f + (colD[g1] * dualScale - cj1.w) * sLe;
    float lb0 = fmaf(xa0, cj0.x, fmaf(xa1, cj0.y, fmaf(xa2, cj0.z, gq0)));
    float lb1 = fmaf(xb0, cj1.x, fmaf(xb1, cj1.y, fmaf(xb2, cj1.z, gq1)));

    float m0 = lb0, m1 = lb1;
    float s0a = 0.f, s0b = 0.f, s1a = 0.f, s1b = 0.f;

    if (!(ub0 + CULL < lb0 && ub1 + CULL < lb1)) {
        for (int p = 0; p < CPART; p += 8) {
            float va[8], vb[8];
#pragma unroll
            for (int k = 0; k < 8; k++) {
                float4 c = shY[p + k];
                va[k] = fmaf(xa0, c.x, fmaf(xa1, c.y, fmaf(xa2, c.z, c.w)));
                vb[k] = fmaf(xb0, c.x, fmaf(xb1, c.y, fmaf(xb2, c.z, c.w)));
            }
            float ca = fmaxf(fmaxf(fmaxf(va[0], va[1]), fmaxf(va[2], va[3])),
                             fmaxf(fmaxf(va[4], va[5]), fmaxf(va[6], va[7])));
            float cb = fmaxf(fmaxf(fmaxf(vb[0], vb[1]), fmaxf(vb[2], vb[3])),
                             fmaxf(fmaxf(vb[4], vb[5]), fmaxf(vb[6], vb[7])));
            // chunk skip: omitted mass < 8*2^-CULL relative to row max (m only grows)
            if (ca > m0 - CULL || cb > m1 - CULL) {
                float mna = fmaxf(m0, ca);
                float mnb = fmaxf(m1, cb);
                float sca = ex2f(m0 - mna);
                float scb = ex2f(m1 - mnb);
                s0a *= sca; s0b *= sca; m0 = mna;
                s1a *= scb; s1b *= scb; m1 = mnb;
#pragma unroll
                for (int k = 0; k < 8; k += 2) {
                    s0a += ex2f(va[k] - m0);
                    s0b += ex2f(va[k + 1] - m0);
                    s1a += ex2f(vb[k] - m1);
                    s1b += ex2f(vb[k + 1] - m1);
                }
            }
        }
    }

    int base = ((task * BB + b) * PARTS + part) * BN;
    *(float2*)&g_pm[base + r0] = make_float2(m0, m1);
    *(float2*)&g_ps[base + r0] = make_float2(s0a + s0b, s1a + s1b);

    // ---- arrival: last block of the (task,b,rowTile) group merges its 256 rows ----
    __syncthreads();
    int grp = bi >> 5;                       // task*32 + b*16 + rowTile
    if (tid == 0) {
        __threadfence();
        int old = atomicAdd(&g_cnt[grp], 1);
        sdoer = (old == PARTS - 1);
        if (old == PARTS - 1) g_cnt[grp] = 0;   // self-reset for next launch/replay
    }
    __syncthreads();
    if (!sdoer) return;

    const float4* rqS = (task == 0 || task == 2) ? gXs4 : gYs4;
#pragma unroll
    for (int rr = 0; rr < 2; rr++) {
        int r = rowTile * RPB + tid + rr * TPB;
        int R = b * BN + r;
        int mb = (task * BB + b) * (PARTS * BN) + r;
        float M = -3.0e38f;
#pragma unroll
        for (int p = 0; p < PARTS; p++) M = fmaxf(M, g_pm[mb + p * BN]);
        float s = 0.f;
#pragma unroll
        for (int p = 0; p < PARTS; p++)
            s = fmaf(g_ps[mb + p * BN], ex2f(g_pm[mb + p * BN] - M), s);
        float val = -eps * LN2 * (-rqS[R].w * sLe + M + lg2f(s));
        if (avg) val = 0.5f * (outAOld[R] + val);
        outA[R] = val;
    }
}

// F = sum_b [ (1/N) sum_i (b_x - a_x) + (1/M) sum_j (a_y - b_y) ]  (order-invariant)
__global__ void reduce_kernel(float* __restrict__ out, int fp) {
    __shared__ float sh[32];
    const float* ax = &g_du[fp][0 * BB * BN];
    const float* by = &g_du[fp][1 * BB * BN];
    const float* bx = &g_du[fp][2 * BB * BN];
    const float* ay = &g_du[fp][3 * BB * BN];
    int tid = threadIdx.x;
    float acc = 0.f;
    for (int i = tid; i < BB * BN; i += blockDim.x)
        acc += (bx[i] - ax[i]) + (ay[i] - by[i]);
    acc *= (1.0f / BN);
#pragma unroll
    for (int o = 16; o; o >>= 1) acc += __shfl_down_sync(0xFFFFFFFFu, acc, o);
    if ((tid & 31) == 0) sh[tid >> 5] = acc;
    __syncthreads();
    if (tid < 32) {
        float v = (tid < (int)(blockDim.x >> 5)) ? sh[tid] : 0.f;
#pragma unroll
        for (int o = 16; o; o >>= 1) v += __shfl_down_sync(0xFFFFFFFFu, v, o);
        if (tid == 0) out[0] = v;
    }
}

extern "C" void kernel_launch(void* const* d_in, const int* in_sizes, int n_in,
                              void* d_out, int out_size) {
    const float* X = (const float*)d_in[0];   // true_data
    const float* Y = (const float*)d_in[1];   // particles
    float* out = (float*)d_out;

    sort_kernel<<<4, 1024>>>(X, Y);           // Morton sort + norms
    bbox_kernel<<<2 * BB * PARTS, CPART>>>(); // per-partition bboxes

    // geomloss eps schedule: [16] + [16,4,1,0.25,0.0625,0.015625,0.00390625] + [0.0025]
    const float epsList[9] = {16.f, 16.f, 4.f, 1.f, 0.25f, 0.0625f,
                              0.015625f, 0.00390625f, 0.0025f};

    const int gridSoft = 4 * BB * ROWTILES * PARTS;   // 4096 blocks
    int p = 0;

    // init (dual term off, assignment); reads buf p, writes buf 1-p
    softmin_kernel<<<gridSoft, TPB>>>(16.f, 0.f, 0, p);
    p ^= 1;

    // eps-scaling loop (symmetrized, averaged updates)
    for (int e = 0; e < 9; e++) {
        softmin_kernel<<<gridSoft, TPB>>>(epsList[e], 1.f, 1, p);
        p ^= 1;
    }

    // final extrapolation at blur^2 (assignment, no averaging)
    softmin_kernel<<<gridSoft, TPB>>>(0.0025f, 1.f, 0, p);
    p ^= 1;

    reduce_kernel<<<1, 256>>>(out, p);
}